// round 6
// baseline (speedup 1.0000x reference)
#include <cuda_runtime.h>
#include <math.h>

// Problem constants
#define BATCH 4096
#define NSTEP 20
#define D0 1024
#define D1 2048
#define D2 2048
#define D3 512
static __device__ __constant__ float LRc = 0.1f;

// GEMM tiling: 128x64 block tile, BK=16, 256 threads, 8x4 micro-tile
#define BM 128
#define BN 64
#define BK 16

// Scratch state (allocation-free rule: __device__ globals)
__device__ float g_r1[BATCH * D1];
__device__ float g_r2[BATCH * D2];
__device__ float g_r3[BATCH * D3];
__device__ float g_e0[BATCH * D0];
__device__ float g_e1[BATCH * D1];
__device__ float g_e2[BATCH * D2];
__device__ float g_acc;

enum { OP_FWD = 0, OP_ERR = 1, OP_UPD = 2, OP_UPD3 = 3 };

// C = A (M,K) @ B, where:
//   BT=false : B is (K,N) row-major  (Y = A @ B)
//   BT=true  : B is (N,K) row-major  (Y = A @ B^T)
// Epilogues:
//   OP_FWD : Out = tanh(acc + aux[n])            (aux = bias)
//   OP_ERR : Out = aux[idx] - tanh(acc)          (aux = r layer above / x)
//   OP_UPD : Out[idx] += LR * (acc - aux[idx])   (aux = error at this layer)
//   OP_UPD3: Out[idx] += LR * (acc - Out[idx])   (top layer, err == r)
template <bool BT, int OP>
__global__ __launch_bounds__(256) void gemm_kernel(
    const float* __restrict__ A, const float* __restrict__ Bm,
    const float* __restrict__ aux, float* __restrict__ Out,
    int M, int N, int K)
{
    __shared__ float As[BK][BM + 4];   // [k][m]
    __shared__ float Bs[BK][BN + 4];   // [k][n]

    const int tid = threadIdx.x;
    const int tx = tid & 15;        // 0..15 -> 4 output cols each
    const int ty = tid >> 4;        // 0..15 -> 8 output rows each
    const int row0 = blockIdx.y * BM;
    const int col0 = blockIdx.x * BN;

    // A-tile load mapping: two float4 per thread (rows aRow and aRow+64)
    const int aRow = tid >> 2;           // 0..63
    const int aCol = (tid & 3) * 4;      // 0,4,8,12
    // B-tile load mappings (one float4 per thread)
    const int bRowNN = tid >> 4;         // 0..15 (k)
    const int bColNN = (tid & 15) * 4;   // n
    const int bRowNT = tid >> 2;         // 0..63 (n)
    const int bColNT = (tid & 3) * 4;    // k

    float acc[8][4] = {};

    for (int k0 = 0; k0 < K; k0 += BK) {
        // Load A tile, transposed into SMEM: As[k][m]
        {
            float4 av = *reinterpret_cast<const float4*>(
                &A[(size_t)(row0 + aRow) * K + (k0 + aCol)]);
            As[aCol + 0][aRow] = av.x;
            As[aCol + 1][aRow] = av.y;
            As[aCol + 2][aRow] = av.z;
            As[aCol + 3][aRow] = av.w;
            float4 av2 = *reinterpret_cast<const float4*>(
                &A[(size_t)(row0 + aRow + 64) * K + (k0 + aCol)]);
            As[aCol + 0][aRow + 64] = av2.x;
            As[aCol + 1][aRow + 64] = av2.y;
            As[aCol + 2][aRow + 64] = av2.z;
            As[aCol + 3][aRow + 64] = av2.w;
        }
        if (!BT) {
            float4 bv = *reinterpret_cast<const float4*>(
                &Bm[(size_t)(k0 + bRowNN) * N + (col0 + bColNN)]);
            *reinterpret_cast<float4*>(&Bs[bRowNN][bColNN]) = bv;
        } else {
            float4 bv = *reinterpret_cast<const float4*>(
                &Bm[(size_t)(col0 + bRowNT) * K + (k0 + bColNT)]);
            Bs[bColNT + 0][bRowNT] = bv.x;
            Bs[bColNT + 1][bRowNT] = bv.y;
            Bs[bColNT + 2][bRowNT] = bv.z;
            Bs[bColNT + 3][bRowNT] = bv.w;
        }
        __syncthreads();

        #pragma unroll
        for (int kk = 0; kk < BK; kk++) {
            float a[8], b[4];
            // 8 consecutive A rows for this thread: two float4 loads
            float4 a0 = *reinterpret_cast<const float4*>(&As[kk][ty * 8 + 0]);
            float4 a1 = *reinterpret_cast<const float4*>(&As[kk][ty * 8 + 4]);
            a[0] = a0.x; a[1] = a0.y; a[2] = a0.z; a[3] = a0.w;
            a[4] = a1.x; a[5] = a1.y; a[6] = a1.z; a[7] = a1.w;
            float4 b0 = *reinterpret_cast<const float4*>(&Bs[kk][tx * 4]);
            b[0] = b0.x; b[1] = b0.y; b[2] = b0.z; b[3] = b0.w;
            #pragma unroll
            for (int i = 0; i < 8; i++)
                #pragma unroll
                for (int j = 0; j < 4; j++)
                    acc[i][j] = fmaf(a[i], b[j], acc[i][j]);
        }
        __syncthreads();
    }

    const float lr = LRc;
    #pragma unroll
    for (int i = 0; i < 8; i++) {
        const int r = row0 + ty * 8 + i;
        #pragma unroll
        for (int j = 0; j < 4; j++) {
            const int c = col0 + tx * 4 + j;
            const size_t idx = (size_t)r * N + c;
            const float v = acc[i][j];
            if (OP == OP_FWD) {
                Out[idx] = tanhf(v + aux[c]);
            } else if (OP == OP_ERR) {
                Out[idx] = aux[idx] - tanhf(v);
            } else if (OP == OP_UPD) {
                Out[idx] = Out[idx] + lr * (v - aux[idx]);
            } else { // OP_UPD3
                const float o = Out[idx];
                Out[idx] = o + lr * (v - o);
            }
        }
    }
}

__global__ void zero_acc_kernel() { g_acc = 0.0f; }

__global__ void sumsq_kernel(const float* __restrict__ x, int n)
{
    float s = 0.0f;
    for (int i = blockIdx.x * blockDim.x + threadIdx.x; i < n;
         i += gridDim.x * blockDim.x) {
        float v = x[i];
        s = fmaf(v, v, s);
    }
    #pragma unroll
    for (int o = 16; o > 0; o >>= 1) s += __shfl_down_sync(0xffffffffu, s, o);
    __shared__ float ws[32];
    const int lane = threadIdx.x & 31, w = threadIdx.x >> 5;
    if (lane == 0) ws[w] = s;
    __syncthreads();
    if (w == 0) {
        s = (lane < (int)(blockDim.x >> 5)) ? ws[lane] : 0.0f;
        #pragma unroll
        for (int o = 16; o > 0; o >>= 1) s += __shfl_down_sync(0xffffffffu, s, o);
        if (lane == 0) atomicAdd(&g_acc, s);
    }
}

__global__ void write_scalar_kernel(float* out)
{
    out[(size_t)BATCH * D3] = 0.5f * g_acc;
}

extern "C" void kernel_launch(void* const* d_in, const int* in_sizes, int n_in,
                              void* d_out, int out_size)
{
    const float* x  = (const float*)d_in[0];
    const float* W0 = (const float*)d_in[1];
    const float* b0 = (const float*)d_in[2];
    const float* W1 = (const float*)d_in[3];
    const float* b1 = (const float*)d_in[4];
    const float* W2 = (const float*)d_in[5];
    const float* b2 = (const float*)d_in[6];
    float* out = (float*)d_out;

    float *r1, *r2, *r3, *e0, *e1, *e2;
    cudaGetSymbolAddress((void**)&r1, g_r1);
    cudaGetSymbolAddress((void**)&r2, g_r2);
    cudaGetSymbolAddress((void**)&r3, g_r3);
    cudaGetSymbolAddress((void**)&e0, g_e0);
    cudaGetSymbolAddress((void**)&e1, g_e1);
    cudaGetSymbolAddress((void**)&e2, g_e2);

    const dim3 blk(256);
    auto grd = [](int M, int N) { return dim3(N / BN, M / BM); };

    // ---- Feedforward init: r_{i+1} = tanh(r_i @ W_i^T + b_i) ----
    gemm_kernel<true, OP_FWD><<<grd(BATCH, D1), blk>>>(x,  W0, b0, r1, BATCH, D1, D0);
    gemm_kernel<true, OP_FWD><<<grd(BATCH, D2), blk>>>(r1, W1, b1, r2, BATCH, D2, D1);
    gemm_kernel<true, OP_FWD><<<grd(BATCH, D3), blk>>>(r2, W2, b2, r3, BATCH, D3, D2);

    // ---- 20 relaxation steps ----
    for (int s = 0; s < NSTEP; s++) {
        // errors (read r, write e):  e_i = r_i - tanh(r_{i+1} @ W_i)
        gemm_kernel<false, OP_ERR><<<grd(BATCH, D2), blk>>>(r3, W2, r2, e2, BATCH, D2, D3);
        gemm_kernel<false, OP_ERR><<<grd(BATCH, D1), blk>>>(r2, W1, r1, e1, BATCH, D1, D2);
        gemm_kernel<false, OP_ERR><<<grd(BATCH, D0), blk>>>(r1, W0, x,  e0, BATCH, D0, D1);
        // updates (read e, update r in place): r_i += LR*(e_{i-1} @ W_{i-1}^T - e_i)
        gemm_kernel<true, OP_UPD ><<<grd(BATCH, D1), blk>>>(e0, W0, e1, r1, BATCH, D1, D0);
        gemm_kernel<true, OP_UPD ><<<grd(BATCH, D2), blk>>>(e1, W1, e2, r2, BATCH, D2, D1);
        gemm_kernel<true, OP_UPD3><<<grd(BATCH, D3), blk>>>(e2, W2, 0,  r3, BATCH, D3, D2);
    }

    // ---- Final errors + total_error = 0.5 * (|e0|^2+|e1|^2+|e2|^2+|r3|^2) ----
    gemm_kernel<false, OP_ERR><<<grd(BATCH, D2), blk>>>(r3, W2, r2, e2, BATCH, D2, D3);
    gemm_kernel<false, OP_ERR><<<grd(BATCH, D1), blk>>>(r2, W1, r1, e1, BATCH, D1, D2);
    gemm_kernel<false, OP_ERR><<<grd(BATCH, D0), blk>>>(r1, W0, x,  e0, BATCH, D0, D1);

    zero_acc_kernel<<<1, 1>>>();
    sumsq_kernel<<<1184, 256>>>(e0, BATCH * D0);
    sumsq_kernel<<<1184, 256>>>(e1, BATCH * D1);
    sumsq_kernel<<<1184, 256>>>(e2, BATCH * D2);
    sumsq_kernel<<<1184, 256>>>(r3, BATCH * D3);

    // ---- Outputs: r3 flattened, then the scalar total_error ----
    cudaMemcpyAsync(out, r3, (size_t)BATCH * D3 * sizeof(float),
                    cudaMemcpyDeviceToDevice);
    if (out_size > BATCH * D3) {
        write_scalar_kernel<<<1, 1>>>(out);
    }
}

// round 7
// speedup vs baseline: 1.9730x; 1.9730x over previous
#include <cuda_runtime.h>
#include <math.h>
#include <stdint.h>

// Problem constants
#define BATCH 4096
#define NSTEP 20
#define D0 1024
#define D1 2048
#define D2 2048
#define D3 512

// GEMM tiling: 128x128 block tile, BK=16, 256 threads, 8 warps (4M x 2N),
// warp tile 32x64 of m16n8k8 tf32 mma.
#define BM 128
#define BN 128
#define BK 16

// Scratch state (allocation-free rule: __device__ globals)
__device__ float g_r1[BATCH * D1];
__device__ float g_r2[BATCH * D2];
__device__ float g_r3[BATCH * D3];
__device__ float g_e0[BATCH * D0];
__device__ float g_e1[BATCH * D1];
__device__ float g_e2[BATCH * D2];
__device__ float g_acc;

enum { OP_FWD = 0, OP_ERR = 1, OP_UPD = 2, OP_UPD3 = 3 };

__device__ __forceinline__ uint32_t f2tf32(float f)
{
    uint32_t u;
    asm("cvt.rna.tf32.f32 %0, %1;" : "=r"(u) : "f"(f));
    return u;
}

__device__ __forceinline__ void mma_tf32(float* c, const uint32_t* a,
                                         uint32_t b0, uint32_t b1)
{
    asm volatile(
        "mma.sync.aligned.m16n8k8.row.col.f32.tf32.tf32.f32 "
        "{%0,%1,%2,%3}, {%4,%5,%6,%7}, {%8,%9}, {%0,%1,%2,%3};"
        : "+f"(c[0]), "+f"(c[1]), "+f"(c[2]), "+f"(c[3])
        : "r"(a[0]), "r"(a[1]), "r"(a[2]), "r"(a[3]), "r"(b0), "r"(b1));
}

// C = A (M,K) @ B, where:
//   BT=false : B is (K,N) row-major  (Y = A @ B)
//   BT=true  : B is (N,K) row-major  (Y = A @ B^T)
// Epilogues:
//   OP_FWD : Out = tanh(acc + aux[n])
//   OP_ERR : Out = aux[idx] - tanh(acc)
//   OP_UPD : Out[idx] += LR * (acc - aux[idx])
//   OP_UPD3: Out[idx] += LR * (acc - Out[idx])
template <bool BT, int OP>
__global__ __launch_bounds__(256, 2) void gemm_tc(
    const float* __restrict__ A, const float* __restrict__ Bm,
    const float* __restrict__ aux, float* __restrict__ Out,
    int M, int N, int K)
{
    constexpr int AS_ST = BK + 4;                  // 20 words: conflict-free frag loads
    constexpr int BS_R  = BT ? BN : BK;
    constexpr int BS_C  = BT ? (BK + 4) : (BN + 4);

    __shared__ uint32_t As[2][BM][AS_ST];
    __shared__ uint32_t Bs[2][BS_R][BS_C];

    const int tid  = threadIdx.x;
    const int lane = tid & 31;
    const int w    = tid >> 5;
    const int wm   = (w & 3) * 32;    // warp M offset in tile
    const int wn   = (w >> 2) * 64;   // warp N offset in tile
    const int g    = lane >> 2;       // groupID (row within m16 / col within n8)
    const int t    = lane & 3;        // threadID_in_group (k index)

    const int row0 = blockIdx.y * BM;
    const int col0 = blockIdx.x * BN;

    // Producer mappings
    const int aRow = tid >> 1;          // 0..127 (also B row for NT)
    const int aK   = (tid & 1) * 8;     // 0 or 8
    const int bKr  = tid >> 4;          // 0..15  (NN: k row)
    const int bNc  = (tid & 15) * 8;    // NN: n col

    const int KT = K / BK;

    float lA[8], lB[8];

    // ---- prologue: load tile 0 ----
    {
        const float* pa = &A[(size_t)(row0 + aRow) * K + aK];
        float4 v0 = *(const float4*)pa;
        float4 v1 = *(const float4*)(pa + 4);
        lA[0]=v0.x; lA[1]=v0.y; lA[2]=v0.z; lA[3]=v0.w;
        lA[4]=v1.x; lA[5]=v1.y; lA[6]=v1.z; lA[7]=v1.w;
        if (BT) {
            const float* pb = &Bm[(size_t)(col0 + aRow) * K + aK];
            float4 u0 = *(const float4*)pb;
            float4 u1 = *(const float4*)(pb + 4);
            lB[0]=u0.x; lB[1]=u0.y; lB[2]=u0.z; lB[3]=u0.w;
            lB[4]=u1.x; lB[5]=u1.y; lB[6]=u1.z; lB[7]=u1.w;
        } else {
            const float* pb = &Bm[(size_t)bKr * N + col0 + bNc];
            float4 u0 = *(const float4*)pb;
            float4 u1 = *(const float4*)(pb + 4);
            lB[0]=u0.x; lB[1]=u0.y; lB[2]=u0.z; lB[3]=u0.w;
            lB[4]=u1.x; lB[5]=u1.y; lB[6]=u1.z; lB[7]=u1.w;
        }
        // cvt + store
        *(uint4*)&As[0][aRow][aK] =
            make_uint4(f2tf32(lA[0]), f2tf32(lA[1]), f2tf32(lA[2]), f2tf32(lA[3]));
        *(uint4*)&As[0][aRow][aK + 4] =
            make_uint4(f2tf32(lA[4]), f2tf32(lA[5]), f2tf32(lA[6]), f2tf32(lA[7]));
        if (BT) {
            *(uint4*)&Bs[0][aRow][aK] =
                make_uint4(f2tf32(lB[0]), f2tf32(lB[1]), f2tf32(lB[2]), f2tf32(lB[3]));
            *(uint4*)&Bs[0][aRow][aK + 4] =
                make_uint4(f2tf32(lB[4]), f2tf32(lB[5]), f2tf32(lB[6]), f2tf32(lB[7]));
        } else {
            *(uint4*)&Bs[0][bKr][bNc] =
                make_uint4(f2tf32(lB[0]), f2tf32(lB[1]), f2tf32(lB[2]), f2tf32(lB[3]));
            *(uint4*)&Bs[0][bKr][bNc + 4] =
                make_uint4(f2tf32(lB[4]), f2tf32(lB[5]), f2tf32(lB[6]), f2tf32(lB[7]));
        }
    }
    __syncthreads();

    float acc[2][8][4];
    #pragma unroll
    for (int mt = 0; mt < 2; mt++)
        #pragma unroll
        for (int nt = 0; nt < 8; nt++)
            #pragma unroll
            for (int i = 0; i < 4; i++) acc[mt][nt][i] = 0.0f;

    for (int kt = 0; kt < KT; kt++) {
        const int p = kt & 1;
        const bool more = (kt + 1 < KT);

        // Issue gmem loads for next tile (in flight during compute)
        if (more) {
            const int k0 = (kt + 1) * BK;
            const float* pa = &A[(size_t)(row0 + aRow) * K + k0 + aK];
            float4 v0 = *(const float4*)pa;
            float4 v1 = *(const float4*)(pa + 4);
            lA[0]=v0.x; lA[1]=v0.y; lA[2]=v0.z; lA[3]=v0.w;
            lA[4]=v1.x; lA[5]=v1.y; lA[6]=v1.z; lA[7]=v1.w;
            if (BT) {
                const float* pb = &Bm[(size_t)(col0 + aRow) * K + k0 + aK];
                float4 u0 = *(const float4*)pb;
                float4 u1 = *(const float4*)(pb + 4);
                lB[0]=u0.x; lB[1]=u0.y; lB[2]=u0.z; lB[3]=u0.w;
                lB[4]=u1.x; lB[5]=u1.y; lB[6]=u1.z; lB[7]=u1.w;
            } else {
                const float* pb = &Bm[(size_t)(k0 + bKr) * N + col0 + bNc];
                float4 u0 = *(const float4*)pb;
                float4 u1 = *(const float4*)(pb + 4);
                lB[0]=u0.x; lB[1]=u0.y; lB[2]=u0.z; lB[3]=u0.w;
                lB[4]=u1.x; lB[5]=u1.y; lB[6]=u1.z; lB[7]=u1.w;
            }
        }

        // Compute on buffer p
        #pragma unroll
        for (int k8 = 0; k8 < BK / 8; k8++) {
            const int kb = k8 * 8;
            uint32_t af[2][4];
            #pragma unroll
            for (int mt = 0; mt < 2; mt++) {
                const int m = wm + mt * 16 + g;
                af[mt][0] = As[p][m][kb + t];
                af[mt][1] = As[p][m + 8][kb + t];
                af[mt][2] = As[p][m][kb + t + 4];
                af[mt][3] = As[p][m + 8][kb + t + 4];
            }
            uint32_t bf[8][2];
            #pragma unroll
            for (int nt = 0; nt < 8; nt++) {
                const int n = wn + nt * 8 + g;
                if (BT) {
                    bf[nt][0] = Bs[p][n][kb + t];
                    bf[nt][1] = Bs[p][n][kb + t + 4];
                } else {
                    bf[nt][0] = Bs[p][kb + t][n];
                    bf[nt][1] = Bs[p][kb + t + 4][n];
                }
            }
            #pragma unroll
            for (int mt = 0; mt < 2; mt++)
                #pragma unroll
                for (int nt = 0; nt < 8; nt++)
                    mma_tf32(acc[mt][nt], af[mt], bf[nt][0], bf[nt][1]);
        }

        // Store next tile into other buffer
        if (more) {
            const int q = p ^ 1;
            *(uint4*)&As[q][aRow][aK] =
                make_uint4(f2tf32(lA[0]), f2tf32(lA[1]), f2tf32(lA[2]), f2tf32(lA[3]));
            *(uint4*)&As[q][aRow][aK + 4] =
                make_uint4(f2tf32(lA[4]), f2tf32(lA[5]), f2tf32(lA[6]), f2tf32(lA[7]));
            if (BT) {
                *(uint4*)&Bs[q][aRow][aK] =
                    make_uint4(f2tf32(lB[0]), f2tf32(lB[1]), f2tf32(lB[2]), f2tf32(lB[3]));
                *(uint4*)&Bs[q][aRow][aK + 4] =
                    make_uint4(f2tf32(lB[4]), f2tf32(lB[5]), f2tf32(lB[6]), f2tf32(lB[7]));
            } else {
                *(uint4*)&Bs[q][bKr][bNc] =
                    make_uint4(f2tf32(lB[0]), f2tf32(lB[1]), f2tf32(lB[2]), f2tf32(lB[3]));
                *(uint4*)&Bs[q][bKr][bNc + 4] =
                    make_uint4(f2tf32(lB[4]), f2tf32(lB[5]), f2tf32(lB[6]), f2tf32(lB[7]));
            }
        }
        __syncthreads();
    }

    // ---- Epilogue ----
    // c0,c1 at (row g, cols t*2, t*2+1); c2,c3 at (row g+8, same cols)
    const float lr = 0.1f;
    #pragma unroll
    for (int mt = 0; mt < 2; mt++) {
        #pragma unroll
        for (int nt = 0; nt < 8; nt++) {
            const int rA = row0 + wm + mt * 16 + g;
            const int rB = rA + 8;
            const int c  = col0 + wn + nt * 8 + t * 2;
            const size_t iA = (size_t)rA * N + c;
            const size_t iB = (size_t)rB * N + c;
            const float* v = acc[mt][nt];

            if (OP == OP_FWD) {
                const float b0 = aux[c], b1 = aux[c + 1];
                float2 oA = make_float2(tanhf(v[0] + b0), tanhf(v[1] + b1));
                float2 oB = make_float2(tanhf(v[2] + b0), tanhf(v[3] + b1));
                *(float2*)&Out[iA] = oA;
                *(float2*)&Out[iB] = oB;
            } else if (OP == OP_ERR) {
                float2 xA = *(const float2*)&aux[iA];
                float2 xB = *(const float2*)&aux[iB];
                *(float2*)&Out[iA] = make_float2(xA.x - tanhf(v[0]), xA.y - tanhf(v[1]));
                *(float2*)&Out[iB] = make_float2(xB.x - tanhf(v[2]), xB.y - tanhf(v[3]));
            } else if (OP == OP_UPD) {
                float2 oA = *(const float2*)&Out[iA];
                float2 oB = *(const float2*)&Out[iB];
                float2 eA = *(const float2*)&aux[iA];
                float2 eB = *(const float2*)&aux[iB];
                *(float2*)&Out[iA] = make_float2(oA.x + lr * (v[0] - eA.x),
                                                 oA.y + lr * (v[1] - eA.y));
                *(float2*)&Out[iB] = make_float2(oB.x + lr * (v[2] - eB.x),
                                                 oB.y + lr * (v[3] - eB.y));
            } else { // OP_UPD3
                float2 oA = *(const float2*)&Out[iA];
                float2 oB = *(const float2*)&Out[iB];
                *(float2*)&Out[iA] = make_float2(oA.x + lr * (v[0] - oA.x),
                                                 oA.y + lr * (v[1] - oA.y));
                *(float2*)&Out[iB] = make_float2(oB.x + lr * (v[2] - oB.x),
                                                 oB.y + lr * (v[3] - oB.y));
            }
        }
    }
}

__global__ void zero_acc_kernel() { g_acc = 0.0f; }

__global__ void sumsq_kernel(const float* __restrict__ x, int n)
{
    float s = 0.0f;
    for (int i = blockIdx.x * blockDim.x + threadIdx.x; i < n;
         i += gridDim.x * blockDim.x) {
        float v = x[i];
        s = fmaf(v, v, s);
    }
    #pragma unroll
    for (int o = 16; o > 0; o >>= 1) s += __shfl_down_sync(0xffffffffu, s, o);
    __shared__ float ws[32];
    const int lane = threadIdx.x & 31, w = threadIdx.x >> 5;
    if (lane == 0) ws[w] = s;
    __syncthreads();
    if (w == 0) {
        s = (lane < (int)(blockDim.x >> 5)) ? ws[lane] : 0.0f;
        #pragma unroll
        for (int o = 16; o > 0; o >>= 1) s += __shfl_down_sync(0xffffffffu, s, o);
        if (lane == 0) atomicAdd(&g_acc, s);
    }
}

__global__ void write_scalar_kernel(float* out)
{
    out[(size_t)BATCH * D3] = 0.5f * g_acc;
}

extern "C" void kernel_launch(void* const* d_in, const int* in_sizes, int n_in,
                              void* d_out, int out_size)
{
    const float* x  = (const float*)d_in[0];
    const float* W0 = (const float*)d_in[1];
    const float* b0 = (const float*)d_in[2];
    const float* W1 = (const float*)d_in[3];
    const float* b1 = (const float*)d_in[4];
    const float* W2 = (const float*)d_in[5];
    const float* b2 = (const float*)d_in[6];
    float* out = (float*)d_out;

    float *r1, *r2, *r3, *e0, *e1, *e2;
    cudaGetSymbolAddress((void**)&r1, g_r1);
    cudaGetSymbolAddress((void**)&r2, g_r2);
    cudaGetSymbolAddress((void**)&r3, g_r3);
    cudaGetSymbolAddress((void**)&e0, g_e0);
    cudaGetSymbolAddress((void**)&e1, g_e1);
    cudaGetSymbolAddress((void**)&e2, g_e2);

    const dim3 blk(256);
    auto grd = [](int M, int N) { return dim3(N / BN, M / BM); };

    // ---- Feedforward init: r_{i+1} = tanh(r_i @ W_i^T + b_i) ----
    gemm_tc<true, OP_FWD><<<grd(BATCH, D1), blk>>>(x,  W0, b0, r1, BATCH, D1, D0);
    gemm_tc<true, OP_FWD><<<grd(BATCH, D2), blk>>>(r1, W1, b1, r2, BATCH, D2, D1);
    gemm_tc<true, OP_FWD><<<grd(BATCH, D3), blk>>>(r2, W2, b2, r3, BATCH, D3, D2);

    // ---- 20 relaxation steps ----
    for (int s = 0; s < NSTEP; s++) {
        // errors: e_i = r_i - tanh(r_{i+1} @ W_i)
        gemm_tc<false, OP_ERR><<<grd(BATCH, D2), blk>>>(r3, W2, r2, e2, BATCH, D2, D3);
        gemm_tc<false, OP_ERR><<<grd(BATCH, D1), blk>>>(r2, W1, r1, e1, BATCH, D1, D2);
        gemm_tc<false, OP_ERR><<<grd(BATCH, D0), blk>>>(r1, W0, x,  e0, BATCH, D0, D1);
        // updates: r_i += LR*(e_{i-1} @ W_{i-1}^T - e_i)
        gemm_tc<true, OP_UPD ><<<grd(BATCH, D1), blk>>>(e0, W0, e1, r1, BATCH, D1, D0);
        gemm_tc<true, OP_UPD ><<<grd(BATCH, D2), blk>>>(e1, W1, e2, r2, BATCH, D2, D1);
        gemm_tc<true, OP_UPD3><<<grd(BATCH, D3), blk>>>(e2, W2, 0,  r3, BATCH, D3, D2);
    }

    // ---- Final errors + total_error ----
    gemm_tc<false, OP_ERR><<<grd(BATCH, D2), blk>>>(r3, W2, r2, e2, BATCH, D2, D3);
    gemm_tc<false, OP_ERR><<<grd(BATCH, D1), blk>>>(r2, W1, r1, e1, BATCH, D1, D2);
    gemm_tc<false, OP_ERR><<<grd(BATCH, D0), blk>>>(r1, W0, x,  e0, BATCH, D0, D1);

    zero_acc_kernel<<<1, 1>>>();
    sumsq_kernel<<<1184, 256>>>(e0, BATCH * D0);
    sumsq_kernel<<<1184, 256>>>(e1, BATCH * D1);
    sumsq_kernel<<<1184, 256>>>(e2, BATCH * D2);
    sumsq_kernel<<<1184, 256>>>(r3, BATCH * D3);

    // ---- Outputs: r3 flattened, then the scalar total_error ----
    cudaMemcpyAsync(out, r3, (size_t)BATCH * D3 * sizeof(float),
                    cudaMemcpyDeviceToDevice);
    if (out_size > BATCH * D3) {
        write_scalar_kernel<<<1, 1>>>(out);
    }
}

// round 13
// speedup vs baseline: 3.2346x; 1.6394x over previous
#include <cuda_runtime.h>
#include <math.h>
#include <stdint.h>

// Problem constants
#define BATCH 4096
#define NSTEP 20
#define D0 1024
#define D1 2048
#define D2 2048
#define D3 512

// GEMM tiling: 128x128 CTA tile, BK=16, 256 threads, 8 warps (4M x 2N),
// warp tile 32x64 of m16n8k8 tf32 mma. 3-stage cp.async pipeline.
#define TM 128
#define TN 128
#define BK 16
#define STAGES 3
#define ROW_W 20                      // words per row (16 data + 4 pad)
#define TILE_W (TM * ROW_W)           // 2560 words per operand tile
#define STAGE_W (2 * TILE_W)          // A + B
#define SMEM_W (STAGES * STAGE_W)
#define SMEM_BYTES (SMEM_W * 4)       // 61440 B

enum { OP_FWD = 0, OP_ERR = 1, OP_UPD = 2, OP_UPD3 = 3 };

// ---------------- scratch state (allocation-free rule: __device__ globals) ----
__device__ float g_r1[BATCH * D1];
__device__ float g_r2[BATCH * D2];
__device__ float g_r3[BATCH * D3];
__device__ float g_e0[BATCH * D0];
__device__ float g_e1[BATCH * D1];
__device__ float g_e2[BATCH * D2];
// tf32-rounded operand copies
__device__ float g_r1r[BATCH * D1];
__device__ float g_r2r[BATCH * D2];
__device__ float g_r3r[BATCH * D3];
__device__ float g_e0r[BATCH * D0];
__device__ float g_e1r[BATCH * D1];
__device__ float g_e2r[BATCH * D2];
__device__ float g_xr[BATCH * D0];
__device__ float g_W0r[D1 * D0];
__device__ float g_W1r[D2 * D1];
__device__ float g_W2r[D3 * D2];
__device__ float g_WT0r[D0 * D1];
__device__ float g_WT1r[D1 * D2];
__device__ float g_WT2r[D2 * D3];
__device__ float g_acc;

// ---------------- helpers ----------------
__device__ __forceinline__ uint32_t f2tf32(float f)
{
    uint32_t u;
    asm("cvt.rna.tf32.f32 %0, %1;" : "=r"(u) : "f"(f));
    return u;
}

__device__ __forceinline__ float roundtf(float f)
{
    return __uint_as_float(f2tf32(f));
}

__device__ __forceinline__ void mma_tf32(float* c, const uint32_t* a,
                                         uint32_t b0, uint32_t b1)
{
    asm volatile(
        "mma.sync.aligned.m16n8k8.row.col.f32.tf32.tf32.f32 "
        "{%0,%1,%2,%3}, {%4,%5,%6,%7}, {%8,%9}, {%0,%1,%2,%3};"
        : "+f"(c[0]), "+f"(c[1]), "+f"(c[2]), "+f"(c[3])
        : "r"(a[0]), "r"(a[1]), "r"(a[2]), "r"(a[3]), "r"(b0), "r"(b1));
}

__device__ __forceinline__ uint32_t smem_u32(const void* p)
{
    uint32_t a;
    asm("{ .reg .u64 t; cvta.to.shared.u64 t, %1; cvt.u32.u64 %0, t; }"
        : "=r"(a) : "l"(p));
    return a;
}

__device__ __forceinline__ void cp_async16(uint32_t saddr, const void* gaddr)
{
    asm volatile("cp.async.cg.shared.global [%0], [%1], 16;"
                 :: "r"(saddr), "l"(gaddr) : "memory");
}

__device__ __forceinline__ void cp_commit()
{
    asm volatile("cp.async.commit_group;" ::: "memory");
}

__device__ __forceinline__ void cp_wait1()
{
    asm volatile("cp.async.wait_group 1;" ::: "memory");
}

// ---------------- fused NT GEMM: D(4096 x N) = A(4096 x K) @ B(N x K)^T ------
struct Seg {
    const float* A;     // (4096, K) tf32-rounded
    const float* B;     // (N, K)    tf32-rounded
    const float* aux;   // bias (FWD) / fp32 array (ERR/UPD) / unused (UPD3)
    float* Out;         // fp32 output (read-modify for UPD/UPD3)
    float* OutR;        // tf32-rounded copy of output
    int N, K, tileOff, tilesN, op;
};
struct FusedArgs { Seg s[3]; int nseg; };

__device__ __forceinline__ void issue_tile(const float* __restrict__ A,
                                           const float* __restrict__ B,
                                           int K, int row0, int col0, int k0,
                                           uint32_t sA, uint32_t sB, int tid)
{
    #pragma unroll
    for (int h = 0; h < 2; h++) {
        const int c = tid + h * 256;
        const int row = c >> 2, j = c & 3;
        cp_async16(sA + (uint32_t)(row * ROW_W + j * 4) * 4,
                   A + (size_t)(row0 + row) * K + k0 + j * 4);
    }
    #pragma unroll
    for (int h = 0; h < 2; h++) {
        const int c = tid + h * 256;
        const int row = c >> 2, j = c & 3;
        cp_async16(sB + (uint32_t)(row * ROW_W + j * 4) * 4,
                   B + (size_t)(col0 + row) * K + k0 + j * 4);
    }
}

__global__ __launch_bounds__(256, 2) void gemm_fused(FusedArgs fa)
{
    extern __shared__ float smem[];
    const int bid = blockIdx.x;

    int si = 0;
    if (fa.nseg > 1 && bid >= fa.s[1].tileOff) si = 1;
    if (fa.nseg > 2 && bid >= fa.s[2].tileOff) si = 2;
    const Seg sg = fa.s[si];

    const int tile = bid - sg.tileOff;
    const int tx = tile % sg.tilesN;
    const int ty = tile / sg.tilesN;
    const int row0 = ty * TM;
    const int col0 = tx * TN;
    const int N = sg.N, K = sg.K;
    const int KT = K / BK;

    const int tid  = threadIdx.x;
    const int lane = tid & 31;
    const int w    = tid >> 5;
    const int g    = lane >> 2;
    const int t    = lane & 3;
    const int wm   = (w & 3) * 32;
    const int wn   = (w >> 2) * 64;

    const uint32_t sbase = smem_u32(smem);

    // prologue: issue first STAGES-1 tiles
    #pragma unroll
    for (int s = 0; s < STAGES - 1; s++) {
        issue_tile(sg.A, sg.B, K, row0, col0, s * BK,
                   sbase + (uint32_t)(s * STAGE_W) * 4,
                   sbase + (uint32_t)(s * STAGE_W + TILE_W) * 4, tid);
        cp_commit();
    }

    float acc[2][8][4];
    #pragma unroll
    for (int mt = 0; mt < 2; mt++)
        #pragma unroll
        for (int nt = 0; nt < 8; nt++)
            #pragma unroll
            for (int i = 0; i < 4; i++) acc[mt][nt][i] = 0.0f;

    for (int kt = 0; kt < KT; kt++) {
        cp_wait1();
        __syncthreads();

        const int knext = kt + STAGES - 1;
        if (knext < KT) {
            const int sn = knext % STAGES;
            issue_tile(sg.A, sg.B, K, row0, col0, knext * BK,
                       sbase + (uint32_t)(sn * STAGE_W) * 4,
                       sbase + (uint32_t)(sn * STAGE_W + TILE_W) * 4, tid);
        }
        cp_commit();

        const int s = kt % STAGES;
        const uint32_t* As = (const uint32_t*)smem + s * STAGE_W;
        const uint32_t* Bs = As + TILE_W;

        #pragma unroll
        for (int k8 = 0; k8 < BK / 8; k8++) {
            const int kb = k8 * 8;
            uint32_t af[2][4], bf[8][2];
            #pragma unroll
            for (int mt = 0; mt < 2; mt++) {
                const int m = wm + mt * 16 + g;
                af[mt][0] = As[m * ROW_W + kb + t];
                af[mt][1] = As[(m + 8) * ROW_W + kb + t];
                af[mt][2] = As[m * ROW_W + kb + t + 4];
                af[mt][3] = As[(m + 8) * ROW_W + kb + t + 4];
            }
            #pragma unroll
            for (int nt = 0; nt < 8; nt++) {
                const int n = wn + nt * 8 + g;
                bf[nt][0] = Bs[n * ROW_W + kb + t];
                bf[nt][1] = Bs[n * ROW_W + kb + t + 4];
            }
            #pragma unroll
            for (int mt = 0; mt < 2; mt++)
                #pragma unroll
                for (int nt = 0; nt < 8; nt++)
                    mma_tf32(acc[mt][nt], af[mt], bf[nt][0], bf[nt][1]);
        }
    }

    // ---- epilogue ----
    const float lr = 0.1f;
    #pragma unroll
    for (int mt = 0; mt < 2; mt++) {
        #pragma unroll
        for (int nt = 0; nt < 8; nt++) {
            const int rA = row0 + wm + mt * 16 + g;
            const int rB = rA + 8;
            const int c  = col0 + wn + nt * 8 + t * 2;
            const size_t iA = (size_t)rA * N + c;
            const size_t iB = (size_t)rB * N + c;
            const float* v = acc[mt][nt];
            float2 oA, oB;
            if (sg.op == OP_FWD) {
                const float b0v = sg.aux[c], b1v = sg.aux[c + 1];
                oA = make_float2(tanhf(v[0] + b0v), tanhf(v[1] + b1v));
                oB = make_float2(tanhf(v[2] + b0v), tanhf(v[3] + b1v));
            } else if (sg.op == OP_ERR) {
                float2 xA = *(const float2*)&sg.aux[iA];
                float2 xB = *(const float2*)&sg.aux[iB];
                oA = make_float2(xA.x - tanhf(v[0]), xA.y - tanhf(v[1]));
                oB = make_float2(xB.x - tanhf(v[2]), xB.y - tanhf(v[3]));
            } else if (sg.op == OP_UPD) {
                float2 pA = *(const float2*)&sg.Out[iA];
                float2 pB = *(const float2*)&sg.Out[iB];
                float2 eA = *(const float2*)&sg.aux[iA];
                float2 eB = *(const float2*)&sg.aux[iB];
                oA = make_float2(pA.x + lr * (v[0] - eA.x), pA.y + lr * (v[1] - eA.y));
                oB = make_float2(pB.x + lr * (v[2] - eB.x), pB.y + lr * (v[3] - eB.y));
            } else { // OP_UPD3
                float2 pA = *(const float2*)&sg.Out[iA];
                float2 pB = *(const float2*)&sg.Out[iB];
                oA = make_float2(pA.x + lr * (v[0] - pA.x), pA.y + lr * (v[1] - pA.y));
                oB = make_float2(pB.x + lr * (v[2] - pB.x), pB.y + lr * (v[3] - pB.y));
            }
            *(float2*)&sg.Out[iA] = oA;
            *(float2*)&sg.Out[iB] = oB;
            *(float2*)&sg.OutR[iA] = make_float2(roundtf(oA.x), roundtf(oA.y));
            *(float2*)&sg.OutR[iB] = make_float2(roundtf(oB.x), roundtf(oB.y));
        }
    }
}

// ---------------- prep kernels ----------------
__global__ void round_copy(const float* __restrict__ s, float* __restrict__ d, int n)
{
    for (int i = blockIdx.x * blockDim.x + threadIdx.x; i < n;
         i += gridDim.x * blockDim.x)
        d[i] = roundtf(s[i]);
}

// T (C x R) = round(S (R x C)^T)
__global__ void transpose_round(const float* __restrict__ S, float* __restrict__ T,
                                int R, int C)
{
    __shared__ float t[32][33];
    const int x = blockIdx.x * 32 + threadIdx.x;
    const int y0 = blockIdx.y * 32;
    #pragma unroll
    for (int j = threadIdx.y; j < 32; j += 8)
        t[j][threadIdx.x] = S[(size_t)(y0 + j) * C + x];
    __syncthreads();
    const int x2 = y0 + threadIdx.x;
    #pragma unroll
    for (int j = threadIdx.y; j < 32; j += 8)
        T[(size_t)(blockIdx.x * 32 + j) * R + x2] = roundtf(t[threadIdx.x][j]);
}

// ---------------- reduction ----------------
__global__ void zero_acc_kernel() { g_acc = 0.0f; }

__global__ void sumsq_kernel(const float* __restrict__ x, int n)
{
    float s = 0.0f;
    for (int i = blockIdx.x * blockDim.x + threadIdx.x; i < n;
         i += gridDim.x * blockDim.x) {
        float v = x[i];
        s = fmaf(v, v, s);
    }
    #pragma unroll
    for (int o = 16; o > 0; o >>= 1) s += __shfl_down_sync(0xffffffffu, s, o);
    __shared__ float ws[32];
    const int lane = threadIdx.x & 31, w = threadIdx.x >> 5;
    if (lane == 0) ws[w] = s;
    __syncthreads();
    if (w == 0) {
        s = (lane < (int)(blockDim.x >> 5)) ? ws[lane] : 0.0f;
        #pragma unroll
        for (int o = 16; o > 0; o >>= 1) s += __shfl_down_sync(0xffffffffu, s, o);
        if (lane == 0) atomicAdd(&g_acc, s);
    }
}

__global__ void write_scalar_kernel(float* out)
{
    out[(size_t)BATCH * D3] = 0.5f * g_acc;
}

// ---------------- host ----------------
static inline Seg mkseg(const float* A, const float* B, const float* aux,
                        float* Out, float* OutR, int N, int K, int off, int op)
{
    Seg s;
    s.A = A; s.B = B; s.aux = aux; s.Out = Out; s.OutR = OutR;
    s.N = N; s.K = K; s.tileOff = off; s.tilesN = N / TN; s.op = op;
    return s;
}

extern "C" void kernel_launch(void* const* d_in, const int* in_sizes, int n_in,
                              void* d_out, int out_size)
{
    const float* x  = (const float*)d_in[0];
    const float* W0 = (const float*)d_in[1];
    const float* b0 = (const float*)d_in[2];
    const float* W1 = (const float*)d_in[3];
    const float* b1 = (const float*)d_in[4];
    const float* W2 = (const float*)d_in[5];
    const float* b2 = (const float*)d_in[6];
    float* out = (float*)d_out;

    float *r1, *r2, *r3, *e0, *e1, *e2;
    float *r1r, *r2r, *r3r, *e0r, *e1r, *e2r, *xr;
    float *W0r, *W1r, *W2r, *WT0r, *WT1r, *WT2r;
    cudaGetSymbolAddress((void**)&r1, g_r1);
    cudaGetSymbolAddress((void**)&r2, g_r2);
    cudaGetSymbolAddress((void**)&r3, g_r3);
    cudaGetSymbolAddress((void**)&e0, g_e0);
    cudaGetSymbolAddress((void**)&e1, g_e1);
    cudaGetSymbolAddress((void**)&e2, g_e2);
    cudaGetSymbolAddress((void**)&r1r, g_r1r);
    cudaGetSymbolAddress((void**)&r2r, g_r2r);
    cudaGetSymbolAddress((void**)&r3r, g_r3r);
    cudaGetSymbolAddress((void**)&e0r, g_e0r);
    cudaGetSymbolAddress((void**)&e1r, g_e1r);
    cudaGetSymbolAddress((void**)&e2r, g_e2r);
    cudaGetSymbolAddress((void**)&xr, g_xr);
    cudaGetSymbolAddress((void**)&W0r, g_W0r);
    cudaGetSymbolAddress((void**)&W1r, g_W1r);
    cudaGetSymbolAddress((void**)&W2r, g_W2r);
    cudaGetSymbolAddress((void**)&WT0r, g_WT0r);
    cudaGetSymbolAddress((void**)&WT1r, g_WT1r);
    cudaGetSymbolAddress((void**)&WT2r, g_WT2r);

    cudaFuncSetAttribute(gemm_fused, cudaFuncAttributeMaxDynamicSharedMemorySize,
                         SMEM_BYTES);

    const dim3 tblk(32, 8);

    // ---- prep: tf32-rounded weights / transposed weights / x ----
    round_copy<<<512, 256>>>(x,  xr,  BATCH * D0);
    round_copy<<<512, 256>>>(W0, W0r, D1 * D0);
    round_copy<<<512, 256>>>(W1, W1r, D2 * D1);
    round_copy<<<512, 256>>>(W2, W2r, D3 * D2);
    transpose_round<<<dim3(D0 / 32, D1 / 32), tblk>>>(W0, WT0r, D1, D0);
    transpose_round<<<dim3(D1 / 32, D2 / 32), tblk>>>(W1, WT1r, D2, D1);
    transpose_round<<<dim3(D2 / 32, D3 / 32), tblk>>>(W2, WT2r, D3, D2);

    // ---- feedforward init: r_{i+1} = tanh(r_i @ W_i^T + b_i) ----
    {
        FusedArgs a{}; a.nseg = 1;
        a.s[0] = mkseg(xr, W0r, b0, r1, r1r, D1, D0, 0, OP_FWD);
        gemm_fused<<<(D1 / TN) * 32, 256, SMEM_BYTES>>>(a);
    }
    {
        FusedArgs a{}; a.nseg = 1;
        a.s[0] = mkseg(r1r, W1r, b1, r2, r2r, D2, D1, 0, OP_FWD);
        gemm_fused<<<(D2 / TN) * 32, 256, SMEM_BYTES>>>(a);
    }
    {
        FusedArgs a{}; a.nseg = 1;
        a.s[0] = mkseg(r2r, W2r, b2, r3, r3r, D3, D2, 0, OP_FWD);
        gemm_fused<<<(D3 / TN) * 32, 256, SMEM_BYTES>>>(a);
    }

    // fused ERR: e1 = r1 - tanh(r2@W1), e0 = x - tanh(r1@W0), e2 = r2 - tanh(r3@W2)
    FusedArgs ferr{}; ferr.nseg = 3;
    {
        int off = 0;
        ferr.s[0] = mkseg(r2r, WT1r, r1, e1, e1r, D1, D2, off, OP_ERR);
        off += (D1 / TN) * 32;
        ferr.s[1] = mkseg(r1r, WT0r, x, e0, e0r, D0, D1, off, OP_ERR);
        off += (D0 / TN) * 32;
        ferr.s[2] = mkseg(r3r, WT2r, r2, e2, e2r, D2, D3, off, OP_ERR);
    }
    const int errGrid = (D1 / TN) * 32 + (D0 / TN) * 32 + (D2 / TN) * 32;

    // fused UPD: r2 += lr*(e1@W1^T - e2), r1 += lr*(e0@W0^T - e1), r3 += lr*(e2@W2^T - r3)
    FusedArgs fupd{}; fupd.nseg = 3;
    {
        int off = 0;
        fupd.s[0] = mkseg(e1r, W1r, e2, r2, r2r, D2, D1, off, OP_UPD);
        off += (D2 / TN) * 32;
        fupd.s[1] = mkseg(e0r, W0r, e1, r1, r1r, D1, D0, off, OP_UPD);
        off += (D1 / TN) * 32;
        fupd.s[2] = mkseg(e2r, W2r, 0, r3, r3r, D3, D2, off, OP_UPD3);
    }
    const int updGrid = (D2 / TN) * 32 + (D1 / TN) * 32 + (D3 / TN) * 32;

    // ---- 20 relaxation steps ----
    for (int s = 0; s < NSTEP; s++) {
        gemm_fused<<<errGrid, 256, SMEM_BYTES>>>(ferr);
        gemm_fused<<<updGrid, 256, SMEM_BYTES>>>(fupd);
    }

    // ---- final errors + total_error ----
    gemm_fused<<<errGrid, 256, SMEM_BYTES>>>(ferr);

    zero_acc_kernel<<<1, 1>>>();
    sumsq_kernel<<<1184, 256>>>(e0, BATCH * D0);
    sumsq_kernel<<<1184, 256>>>(e1, BATCH * D1);
    sumsq_kernel<<<1184, 256>>>(e2, BATCH * D2);
    sumsq_kernel<<<1184, 256>>>(r3, BATCH * D3);

    // ---- outputs: r3 flattened, then the scalar total_error ----
    cudaMemcpyAsync(out, r3, (size_t)BATCH * D3 * sizeof(float),
                    cudaMemcpyDeviceToDevice);
    if (out_size > BATCH * D3) {
        write_scalar_kernel<<<1, 1>>>(out);
    }
}